// round 1
// baseline (speedup 1.0000x reference)
#include <cuda_runtime.h>
#include <cuda_bf16.h>
#include <math.h>

// Problem constants (fixed by the reference)
#define N_NODES 100000
#define N_EDGES 800000
#define D 64
#define D_FEAT 10
#define EPS 1e-8f

// ---------------- static device scratch (no allocation allowed) ----------------
__device__ float g_emb0[N_NODES * D];
__device__ float g_emb1[N_NODES * D];
__device__ int   g_indeg[N_NODES];
__device__ int   g_off[N_NODES + 1];
__device__ int   g_cursor[N_NODES];
__device__ int   g_srcs[N_EDGES];

// ---------------- CSR build ----------------
__global__ void zero_indeg_kernel() {
    int i = blockIdx.x * blockDim.x + threadIdx.x;
    if (i < N_NODES) g_indeg[i] = 0;
}

__global__ void count_kernel(const int2* __restrict__ edges) {
    int e = blockIdx.x * blockDim.x + threadIdx.x;
    if (e < N_EDGES) {
        int2 ed = edges[e];
        atomicAdd(&g_indeg[ed.y], 1);
    }
}

// Single-block scan over 100k counts -> exclusive offsets (+ cursor init)
#define SCAN_T 1024
#define SCAN_CHUNK ((N_NODES + SCAN_T - 1) / SCAN_T)  // 98

__global__ void scan_kernel() {
    __shared__ int warp_sums[32];
    int tid  = threadIdx.x;
    int lane = tid & 31;
    int wid  = tid >> 5;

    int start = tid * SCAN_CHUNK;
    int end   = min(start + SCAN_CHUNK, N_NODES);

    int total = 0;
    for (int i = start; i < end; i++) total += g_indeg[i];

    // inclusive warp scan of per-thread totals
    int v = total;
    #pragma unroll
    for (int o = 1; o < 32; o <<= 1) {
        int n = __shfl_up_sync(0xFFFFFFFFu, v, o);
        if (lane >= o) v += n;
    }
    if (lane == 31) warp_sums[wid] = v;
    __syncthreads();
    if (wid == 0) {
        int w = warp_sums[lane];
        #pragma unroll
        for (int o = 1; o < 32; o <<= 1) {
            int n = __shfl_up_sync(0xFFFFFFFFu, w, o);
            if (lane >= o) w += n;
        }
        warp_sums[lane] = w;
    }
    __syncthreads();

    int excl = v - total + (wid > 0 ? warp_sums[wid - 1] : 0);

    int run = excl;
    for (int i = start; i < end; i++) {
        int c = g_indeg[i];
        g_off[i]    = run;
        g_cursor[i] = run;
        run += c;
    }
    if (tid == SCAN_T - 1) g_off[N_NODES] = run;  // == N_EDGES
}

__global__ void place_kernel(const int2* __restrict__ edges) {
    int e = blockIdx.x * blockDim.x + threadIdx.x;
    if (e < N_EDGES) {
        int2 ed = edges[e];
        int slot = atomicAdd(&g_cursor[ed.y], 1);
        g_srcs[slot] = ed.x;
    }
}

// ---------------- init: embeds = node_emb[nodes] + features @ feat_W^T + feat_b ----------------
__global__ void init_kernel(const int* __restrict__ nodes,
                            const float* __restrict__ features,
                            const float* __restrict__ node_emb,
                            const float* __restrict__ feat_W,
                            const float* __restrict__ feat_b) {
    int idx = blockIdx.x * blockDim.x + threadIdx.x;
    if (idx >= N_NODES * D) return;
    int node = idx >> 6;
    int d    = idx & 63;

    int tok = nodes[node];
    float acc = node_emb[tok * D + d] + feat_b[d];
    const float* f  = features + node * D_FEAT;
    const float* wr = feat_W + d * D_FEAT;
    #pragma unroll
    for (int k = 0; k < D_FEAT; k++) acc += f[k] * wr[k];
    g_emb0[idx] = acc;
}

// ---------------- fused layer: out = relu((in + gather_sum(in)) @ W^T + b) ----------------
// Persistent grid-stride kernel; W column (64 fp32) lives in registers per thread.
__global__ __launch_bounds__(256, 2)
void layer_kernel(const float* __restrict__ in, float* __restrict__ out,
                  const float* __restrict__ W, const float* __restrict__ bvec) {
    __shared__ __align__(16) float xs[4][D];

    int tid = threadIdx.x;
    int sub = tid >> 6;   // which of 4 nodes this thread serves
    int t   = tid & 63;   // output dim owned by this thread

    // Load this thread's W column: out[t] needs W[t][d] for all d (contiguous row)
    float w[D];
    const float4* Wrow = (const float4*)(W + t * D);
    #pragma unroll
    for (int k = 0; k < 16; k++) {
        float4 v = Wrow[k];
        w[4 * k + 0] = v.x; w[4 * k + 1] = v.y;
        w[4 * k + 2] = v.z; w[4 * k + 3] = v.w;
    }
    float bt = bvec[t];

    for (int base = blockIdx.x * 4; base < N_NODES; base += gridDim.x * 4) {
        int node = base + sub;  // N_NODES % 4 == 0 and base % 4 == 0 -> always valid

        // gather: self + sum of in-neighbors (batch src loads for MLP)
        float acc = in[node * D + t];
        int s0 = g_off[node], s1 = g_off[node + 1];
        int j = s0;
        for (; j + 8 <= s1; j += 8) {
            int a0 = g_srcs[j + 0], a1 = g_srcs[j + 1], a2 = g_srcs[j + 2], a3 = g_srcs[j + 3];
            int a4 = g_srcs[j + 4], a5 = g_srcs[j + 5], a6 = g_srcs[j + 6], a7 = g_srcs[j + 7];
            float r0 = in[a0 * D + t], r1 = in[a1 * D + t], r2 = in[a2 * D + t], r3 = in[a3 * D + t];
            float r4 = in[a4 * D + t], r5 = in[a5 * D + t], r6 = in[a6 * D + t], r7 = in[a7 * D + t];
            acc += ((r0 + r1) + (r2 + r3)) + ((r4 + r5) + (r6 + r7));
        }
        for (; j < s1; j++) acc += in[g_srcs[j] * D + t];

        xs[sub][t] = acc;
        __syncthreads();

        // GEMV: o = b[t] + sum_d x[d] * W[t][d]
        float o0 = bt, o1 = 0.f, o2 = 0.f, o3 = 0.f;
        #pragma unroll
        for (int d = 0; d < D; d += 16) {
            float4 x0 = *(const float4*)&xs[sub][d + 0];
            float4 x1 = *(const float4*)&xs[sub][d + 4];
            float4 x2 = *(const float4*)&xs[sub][d + 8];
            float4 x3 = *(const float4*)&xs[sub][d + 12];
            o0 += x0.x * w[d + 0] + x0.y * w[d + 1] + x0.z * w[d + 2] + x0.w * w[d + 3];
            o1 += x1.x * w[d + 4] + x1.y * w[d + 5] + x1.z * w[d + 6] + x1.w * w[d + 7];
            o2 += x2.x * w[d + 8] + x2.y * w[d + 9] + x2.z * w[d + 10] + x2.w * w[d + 11];
            o3 += x3.x * w[d + 12] + x3.y * w[d + 13] + x3.z * w[d + 14] + x3.w * w[d + 15];
        }
        out[node * D + t] = fmaxf((o0 + o1) + (o2 + o3), 0.f);
        __syncthreads();  // xs reuse guard for next iteration
    }
}

// ---------------- final: cosine similarity with pattern vector ----------------
__global__ void final_kernel(const float* __restrict__ emb,
                             const float* __restrict__ pattern_emb,
                             const int* __restrict__ pid,
                             float* __restrict__ out) {
    int gtid = blockIdx.x * blockDim.x + threadIdx.x;
    int node = gtid >> 5;
    int lane = threadIdx.x & 31;
    if (node >= N_NODES) return;

    const float2* p = (const float2*)(pattern_emb + (*pid) * D);
    float2 pv = p[lane];
    float2 e  = ((const float2*)(emb + node * D))[lane];

    float num = e.x * pv.x + e.y * pv.y;
    float sq  = e.x * e.x + e.y * e.y;
    float psq = pv.x * pv.x + pv.y * pv.y;

    #pragma unroll
    for (int o = 16; o > 0; o >>= 1) {
        num += __shfl_xor_sync(0xFFFFFFFFu, num, o);
        sq  += __shfl_xor_sync(0xFFFFFFFFu, sq, o);
        psq += __shfl_xor_sync(0xFFFFFFFFu, psq, o);
    }
    if (lane == 0) {
        float denom = fmaxf(sqrtf(sq), EPS) * fmaxf(sqrtf(psq), EPS);
        out[node] = num / denom;
    }
}

// ---------------- launch ----------------
extern "C" void kernel_launch(void* const* d_in, const int* in_sizes, int n_in,
                              void* d_out, int out_size) {
    const int*   nodes       = (const int*)d_in[0];
    const int2*  edges       = (const int2*)d_in[1];
    const float* features    = (const float*)d_in[2];
    const float* node_emb    = (const float*)d_in[3];
    const float* feat_W      = (const float*)d_in[4];
    const float* feat_b      = (const float*)d_in[5];
    const float* conv1_W     = (const float*)d_in[6];
    const float* conv1_b     = (const float*)d_in[7];
    const float* pattern_emb = (const float*)d_in[8];
    const int*   pattern_id  = (const int*)d_in[9];
    float*       out         = (float*)d_out;

    // CSR build (by destination)
    zero_indeg_kernel<<<(N_NODES + 255) / 256, 256>>>();
    count_kernel<<<(N_EDGES + 255) / 256, 256>>>(edges);
    scan_kernel<<<1, SCAN_T>>>();
    place_kernel<<<(N_EDGES + 255) / 256, 256>>>(edges);

    // init embeddings
    init_kernel<<<(N_NODES * D + 255) / 256, 256>>>(nodes, features, node_emb, feat_W, feat_b);

    // two GNN layers (ping-pong buffers), persistent grid
    float* e0; float* e1;
    cudaGetSymbolAddress((void**)&e0, g_emb0);
    cudaGetSymbolAddress((void**)&e1, g_emb1);
    const int LAYER_GRID = 304;  // 2 * 152 SMs
    layer_kernel<<<LAYER_GRID, 256>>>(e0, e1, conv1_W, conv1_b);
    layer_kernel<<<LAYER_GRID, 256>>>(e1, e0, conv1_W, conv1_b);

    // cosine similarity
    final_kernel<<<(N_NODES * 32 + 255) / 256, 256>>>(e0, pattern_emb, pattern_id, out);
}

// round 2
// speedup vs baseline: 1.6222x; 1.6222x over previous
#include <cuda_runtime.h>
#include <cuda_bf16.h>
#include <math.h>

#define N_NODES 100000
#define N_EDGES 800000
#define D 64
#define D_FEAT 10
#define VOCAB 100
#define EPS 1e-8f

// ---------------- static device scratch ----------------
__device__ float g_z[N_NODES * D];      // z (pre-aggregation linear output)
__device__ float g_h[N_NODES * D];      // hidden activations
__device__ int   g_indeg[N_NODES];
__device__ int   g_off[N_NODES + 1];
__device__ int   g_cursor[N_NODES];
__device__ int   g_srcs[N_EDGES];
__device__ float g_nv[VOCAB * D];       // node_emb @ conv1_W^T
__device__ float g_fw2t[D_FEAT * D];    // (conv1_W @ feat_W) transposed: [k][d]
__device__ float g_c[D];                // conv1_W @ feat_b

// ---------------- CSR build ----------------
__global__ void zero_indeg_kernel() {
    int i = blockIdx.x * blockDim.x + threadIdx.x;
    if (i < N_NODES) g_indeg[i] = 0;
}

__global__ void count_kernel(const int2* __restrict__ edges) {
    int e = blockIdx.x * blockDim.x + threadIdx.x;
    if (e < N_EDGES) atomicAdd(&g_indeg[edges[e].y], 1);
}

#define SCAN_T 1024
#define SCAN_CHUNK ((N_NODES + SCAN_T - 1) / SCAN_T)  // 98

__global__ void scan_kernel() {
    __shared__ int warp_sums[32];
    int tid  = threadIdx.x;
    int lane = tid & 31;
    int wid  = tid >> 5;

    int start = tid * SCAN_CHUNK;
    int end   = min(start + SCAN_CHUNK, N_NODES);

    int total = 0;
    for (int i = start; i < end; i++) total += g_indeg[i];

    int v = total;
    #pragma unroll
    for (int o = 1; o < 32; o <<= 1) {
        int n = __shfl_up_sync(0xFFFFFFFFu, v, o);
        if (lane >= o) v += n;
    }
    if (lane == 31) warp_sums[wid] = v;
    __syncthreads();
    if (wid == 0) {
        int w = warp_sums[lane];
        #pragma unroll
        for (int o = 1; o < 32; o <<= 1) {
            int n = __shfl_up_sync(0xFFFFFFFFu, w, o);
            if (lane >= o) w += n;
        }
        warp_sums[lane] = w;
    }
    __syncthreads();

    int excl = v - total + (wid > 0 ? warp_sums[wid - 1] : 0);

    int run = excl;
    for (int i = start; i < end; i++) {
        int c = g_indeg[i];
        g_off[i]    = run;
        g_cursor[i] = run;
        run += c;
    }
    if (tid == SCAN_T - 1) g_off[N_NODES] = run;
}

__global__ void place_kernel(const int2* __restrict__ edges) {
    int e = blockIdx.x * blockDim.x + threadIdx.x;
    if (e < N_EDGES) {
        int2 ed = edges[e];
        int slot = atomicAdd(&g_cursor[ed.y], 1);
        g_srcs[slot] = ed.x;
    }
}

// ---------------- precompute: folded weights ----------------
// block 0:      g_fw2t[k][d] = sum_j W[d][j]*feat_W[j][k];  g_c[d] = sum_j W[d][j]*feat_b[j]
// blocks 1..VOCAB: g_nv[v][d] = sum_j node_emb[v][j]*W[d][j]
__global__ void precompute_kernel(const float* __restrict__ node_emb,
                                  const float* __restrict__ feat_W,
                                  const float* __restrict__ feat_b,
                                  const float* __restrict__ W) {
    int d = threadIdx.x;  // 0..63
    if (blockIdx.x == 0) {
        float wrow[D];
        #pragma unroll
        for (int j = 0; j < D; j++) wrow[j] = W[d * D + j];
        #pragma unroll
        for (int k = 0; k < D_FEAT; k++) {
            float s = 0.f;
            #pragma unroll
            for (int j = 0; j < D; j++) s += wrow[j] * feat_W[j * D_FEAT + k];
            g_fw2t[k * D + d] = s;
        }
        float cb = 0.f;
        #pragma unroll
        for (int j = 0; j < D; j++) cb += wrow[j] * feat_b[j];
        g_c[d] = cb;
    } else {
        int v = blockIdx.x - 1;
        __shared__ float se[D];
        se[d] = node_emb[v * D + d];
        __syncthreads();
        float s = 0.f;
        #pragma unroll
        for (int j = 0; j < D; j++) s += W[d * D + j] * se[j];
        g_nv[v * D + d] = s;
    }
}

// ---------------- z1 = nv[nodes] + features @ fw2^T + c ----------------
// one thread per float4 of z1: 1.6M threads
__global__ __launch_bounds__(256)
void z1_kernel(const int* __restrict__ nodes, const float* __restrict__ features) {
    __shared__ float s_fw2t[D_FEAT * D];
    __shared__ float s_c[D];
    int tid = threadIdx.x;
    for (int i = tid; i < D_FEAT * D; i += 256) s_fw2t[i] = g_fw2t[i];
    if (tid < D) s_c[tid] = g_c[tid];
    __syncthreads();

    int q    = blockIdx.x * 256 + tid;   // quad id: [node(16) | dq(4)]
    int node = q >> 4;
    int dq   = (q & 15) * 4;

    int tok = __ldg(&nodes[node]);
    const float* f = features + node * D_FEAT;
    float f0 = f[0], f1 = f[1], f2 = f[2], f3 = f[3], f4 = f[4];
    float f5 = f[5], f6 = f[6], f7 = f[7], f8 = f[8], f9 = f[9];

    float4 acc = *(const float4*)&g_nv[tok * D + dq];
    float4 cc  = *(const float4*)&s_c[dq];
    acc.x += cc.x; acc.y += cc.y; acc.z += cc.z; acc.w += cc.w;

    float fk[D_FEAT] = {f0, f1, f2, f3, f4, f5, f6, f7, f8, f9};
    #pragma unroll
    for (int k = 0; k < D_FEAT; k++) {
        float4 w4 = *(const float4*)&s_fw2t[k * D + dq];
        acc.x += fk[k] * w4.x; acc.y += fk[k] * w4.y;
        acc.z += fk[k] * w4.z; acc.w += fk[k] * w4.w;
    }
    *(float4*)&g_z[node * D + dq] = acc;
}

// ---------------- agg + bias + relu: h = relu(z + A z + b) ----------------
// one warp per node, float2 per lane
__global__ __launch_bounds__(256)
void agg_relu_kernel(const float* __restrict__ z, float* __restrict__ h,
                     const float* __restrict__ bvec) {
    int node = blockIdx.x * 8 + (threadIdx.x >> 5);
    int lane = threadIdx.x & 31;

    float2 acc = *(const float2*)&z[node * D + lane * 2];
    int s0 = g_off[node], s1 = g_off[node + 1];

    for (int base = s0; base < s1; base += 32) {
        int cnt = min(32, s1 - base);
        int idx = (base + lane < s1) ? g_srcs[base + lane] : 0;
        for (int k = 0; k < cnt; k++) {
            int a = __shfl_sync(0xFFFFFFFFu, idx, k);
            float2 v = *(const float2*)&z[a * D + lane * 2];
            acc.x += v.x; acc.y += v.y;
        }
    }
    float2 b2 = *(const float2*)&bvec[lane * 2];
    acc.x = fmaxf(acc.x + b2.x, 0.f);
    acc.y = fmaxf(acc.y + b2.y, 0.f);
    *(float2*)&h[node * D + lane * 2] = acc;
}

// ---------------- GEMM: z = h @ W^T (no bias) ----------------
// 4 teams of 64 threads; W column in regs; 8 nodes per block-iteration
#define GEMM_GRID 500   // 500*8 = 4000 nodes/iter; 100000/4000 = 25 exact
__global__ __launch_bounds__(256, 2)
void gemm_kernel(const float* __restrict__ in, float* __restrict__ out,
                 const float* __restrict__ W) {
    __shared__ __align__(16) float xs[8][D];
    int tid = threadIdx.x;
    int sub = tid >> 6;
    int t   = tid & 63;

    float w[D];
    const float4* Wrow = (const float4*)(W + t * D);
    #pragma unroll
    for (int k = 0; k < 16; k++) {
        float4 v = Wrow[k];
        w[4 * k + 0] = v.x; w[4 * k + 1] = v.y;
        w[4 * k + 2] = v.z; w[4 * k + 3] = v.w;
    }

    for (int base = blockIdx.x * 8; base < N_NODES; base += GEMM_GRID * 8) {
        #pragma unroll
        for (int i = tid; i < 8 * D; i += 256) xs[i >> 6][i & 63] = in[base * D + i];
        __syncthreads();

        #pragma unroll
        for (int r = 0; r < 2; r++) {
            int n = sub * 2 + r;
            float o0 = 0.f, o1 = 0.f, o2 = 0.f, o3 = 0.f;
            #pragma unroll
            for (int d = 0; d < D; d += 16) {
                float4 x0 = *(const float4*)&xs[n][d + 0];
                float4 x1 = *(const float4*)&xs[n][d + 4];
                float4 x2 = *(const float4*)&xs[n][d + 8];
                float4 x3 = *(const float4*)&xs[n][d + 12];
                o0 += x0.x * w[d + 0] + x0.y * w[d + 1] + x0.z * w[d + 2] + x0.w * w[d + 3];
                o1 += x1.x * w[d + 4] + x1.y * w[d + 5] + x1.z * w[d + 6] + x1.w * w[d + 7];
                o2 += x2.x * w[d + 8] + x2.y * w[d + 9] + x2.z * w[d + 10] + x2.w * w[d + 11];
                o3 += x3.x * w[d + 12] + x3.y * w[d + 13] + x3.z * w[d + 14] + x3.w * w[d + 15];
            }
            out[(base + n) * D + t] = (o0 + o1) + (o2 + o3);
        }
        __syncthreads();
    }
}

// ---------------- fused layer-2 agg + relu + cosine ----------------
// row = relu(z[n] + A z[n] + b); out[n] = (row.p) / (max(|row|,eps)*max(|p|,eps))
__global__ __launch_bounds__(256)
void agg_cos_kernel(const float* __restrict__ z,
                    const float* __restrict__ bvec,
                    const float* __restrict__ pattern_emb,
                    const int* __restrict__ pid,
                    float* __restrict__ out) {
    int node = blockIdx.x * 8 + (threadIdx.x >> 5);
    int lane = threadIdx.x & 31;

    float2 acc = *(const float2*)&z[node * D + lane * 2];
    int s0 = g_off[node], s1 = g_off[node + 1];

    for (int base = s0; base < s1; base += 32) {
        int cnt = min(32, s1 - base);
        int idx = (base + lane < s1) ? g_srcs[base + lane] : 0;
        for (int k = 0; k < cnt; k++) {
            int a = __shfl_sync(0xFFFFFFFFu, idx, k);
            float2 v = *(const float2*)&z[a * D + lane * 2];
            acc.x += v.x; acc.y += v.y;
        }
    }
    float2 b2 = *(const float2*)&bvec[lane * 2];
    acc.x = fmaxf(acc.x + b2.x, 0.f);
    acc.y = fmaxf(acc.y + b2.y, 0.f);

    int p_id = __ldg(pid);
    float2 pv = *(const float2*)&pattern_emb[p_id * D + lane * 2];

    float num = acc.x * pv.x + acc.y * pv.y;
    float sq  = acc.x * acc.x + acc.y * acc.y;
    float psq = pv.x * pv.x + pv.y * pv.y;

    #pragma unroll
    for (int o = 16; o > 0; o >>= 1) {
        num += __shfl_xor_sync(0xFFFFFFFFu, num, o);
        sq  += __shfl_xor_sync(0xFFFFFFFFu, sq, o);
        psq += __shfl_xor_sync(0xFFFFFFFFu, psq, o);
    }
    if (lane == 0) {
        float denom = fmaxf(sqrtf(sq), EPS) * fmaxf(sqrtf(psq), EPS);
        out[node] = num / denom;
    }
}

// ---------------- launch ----------------
extern "C" void kernel_launch(void* const* d_in, const int* in_sizes, int n_in,
                              void* d_out, int out_size) {
    const int*   nodes       = (const int*)d_in[0];
    const int2*  edges       = (const int2*)d_in[1];
    const float* features    = (const float*)d_in[2];
    const float* node_emb    = (const float*)d_in[3];
    const float* feat_W      = (const float*)d_in[4];
    const float* feat_b      = (const float*)d_in[5];
    const float* conv1_W     = (const float*)d_in[6];
    const float* conv1_b     = (const float*)d_in[7];
    const float* pattern_emb = (const float*)d_in[8];
    const int*   pattern_id  = (const int*)d_in[9];
    float*       out         = (float*)d_out;

    float* z; float* h;
    cudaGetSymbolAddress((void**)&z, g_z);
    cudaGetSymbolAddress((void**)&h, g_h);

    // CSR build
    zero_indeg_kernel<<<(N_NODES + 255) / 256, 256>>>();
    count_kernel<<<(N_EDGES + 255) / 256, 256>>>(edges);
    scan_kernel<<<1, SCAN_T>>>();
    place_kernel<<<(N_EDGES + 255) / 256, 256>>>(edges);

    // folded weights + z1
    precompute_kernel<<<VOCAB + 1, D>>>(node_emb, feat_W, feat_b, conv1_W);
    z1_kernel<<<(N_NODES * 16) / 256, 256>>>(nodes, features);       // z = e @ W^T

    // layer 1: h = relu(z + A z + b)
    agg_relu_kernel<<<N_NODES / 8, 256>>>(z, h, conv1_b);

    // layer 2: z = h @ W^T, then fused agg+relu+cosine
    gemm_kernel<<<GEMM_GRID, 256>>>(h, z, conv1_W);
    agg_cos_kernel<<<N_NODES / 8, 256>>>(z, conv1_b, pattern_emb, pattern_id, out);
}